// round 1
// baseline (speedup 1.0000x reference)
#include <cuda_runtime.h>
#include <math.h>

// Problem constants
#define EDIM   128      // embed/frequency size
#define LSEQ   512      // seq length
#define NB     16       // batch
#define NFEAT  32       // feature size
#define MFULL  16384    // N*L (real FFT length)
#define HHALF  8192     // half length (packed complex FFT size)
#define FBINS  8193     // rfft bins
#define LAMBDA 0.01f

// Persistent scratch (device globals; no dynamic allocation allowed)
__device__ float  d_Xr[NB][FBINS];
__device__ float  d_Xi[NB][FBINS];
__device__ float  d_H1[NB][EDIM * 8];
__device__ float2 d_tw[HHALF / 2];   // tw[j] = e^{+i*pi*j/4096} = e^{+2*pi*i*j/8192}

__device__ __forceinline__ float sshrink(float v) {
    return v > LAMBDA ? v - LAMBDA : (v < -LAMBDA ? v + LAMBDA : 0.0f);
}

// ---------------------------------------------------------------------------
// Kernel 0: build twiddle table
// ---------------------------------------------------------------------------
__global__ void twiddle_init() {
    int j = blockIdx.x * blockDim.x + threadIdx.x;
    if (j < 4096) {
        float s, c;
        sincospif((float)j * (1.0f / 4096.0f), &s, &c);
        d_tw[j] = make_float2(c, s);
    }
}

// ---------------------------------------------------------------------------
// Kernel 1: forward rfft of xt[b, 0:16384] via packed 8192-pt complex DIT FFT.
// xt[b,m] = x[b, m%512, m/512]. Output: X[b,f], f=0..8192 (ortho norm).
// ---------------------------------------------------------------------------
__global__ void fwd_fft(const float* __restrict__ x) {
    extern __shared__ float2 smf[];
    float2* buf = smf;           // 8192 complex
    float2* twl = smf + 8192;    // 4096 twiddles
    const int b = blockIdx.x;
    const int tid = threadIdx.x;

    for (int j = tid; j < 4096; j += 512) twl[j] = d_tw[j];

    const float* xb = x + b * LSEQ * NFEAT;
    // DIT: input in bit-reversed order -> output natural order
    for (int n = tid; n < HHALF; n += 512) {
        int br = __brev((unsigned)n) >> 19;   // 13-bit bit-reverse
        int m0 = 2 * br, m1 = m0 + 1;
        float a = xb[(m0 & 511) * NFEAT + (m0 >> 9)];
        float c = xb[(m1 & 511) * NFEAT + (m1 >> 9)];
        buf[n] = make_float2(a, c);
    }
    __syncthreads();

    // 13 DIT stages, forward (e^{-}) twiddles = conj(table)
    for (int s = 0; s < 13; s++) {
        int half = 1 << s;
        for (int t = tid; t < 4096; t += 512) {
            int j = t & (half - 1);
            int i = ((t >> s) << (s + 1)) + j;
            float2 w = twl[j << (12 - s)];
            float2 u = buf[i];
            float2 v = buf[i + half];
            float vr = v.x * w.x + v.y * w.y;     // v * conj(w)
            float vi = v.y * w.x - v.x * w.y;
            buf[i]        = make_float2(u.x + vr, u.y + vi);
            buf[i + half] = make_float2(u.x - vr, u.y - vi);
        }
        __syncthreads();
    }

    // Recombine packed FFT -> rfft bins. Z = (0.5/sqrt(M)) * (A - i*w*B),
    // w = e^{-i*pi*f/8192}
    const float sc = 0.5f / 128.0f;
    for (int f = tid; f < FBINS; f += 512) {
        float2 Yf = buf[f & (HHALF - 1)];
        float2 Yh = buf[(HHALF - f) & (HHALF - 1)];
        float Ax = Yf.x + Yh.x, Ay = Yf.y - Yh.y;
        float Bx = Yf.x - Yh.x, By = Yf.y + Yh.y;
        float ss, cc;
        sincospif((float)f * (1.0f / 8192.0f), &ss, &cc);
        d_Xr[b][f] = sc * (Ax + cc * By - ss * Bx);
        d_Xi[b][f] = sc * (Ay - cc * Bx - ss * By);
    }
}

// ---------------------------------------------------------------------------
// Kernel 2 (fused): per (b,e): fourierGC chain -> Hermitian pack -> in-place
// 8192-pt DIF IFFT -> first 512 real samples -> +bias -> dot with emb10.
// Grid: (EDIM, NB), 512 threads.
// ---------------------------------------------------------------------------
__global__ void gc_ifft(const float* __restrict__ x, const float* __restrict__ emb,
                        const float* __restrict__ w0, const float* __restrict__ b0,
                        const float* __restrict__ w1, const float* __restrict__ b1,
                        const float* __restrict__ w2, const float* __restrict__ b2,
                        const float* __restrict__ emb10) {
    extern __shared__ float2 smg[];
    float2* zb  = smg;          // 8193 complex (padded to 8200)
    float2* twl = smg + 8200;   // 4096 twiddles
    const int e = blockIdx.x;
    const int b = blockIdx.y;
    const int tid = threadIdx.x;

    for (int j = tid; j < 4096; j += 512) twl[j] = d_tw[j];

    const float embe = emb[e];
    const float d00 = w0[e * 129],        d01 = w0[16384 + e * 129];
    const float b00 = b0[e],              b01 = b0[128 + e];
    const float d10 = w1[e * 129],        d11 = w1[16384 + e * 129];
    const float b10 = b1[e],              b11 = b1[128 + e];
    const float d20 = w2[e * 129],        d21 = w2[16384 + e * 129];
    const float b20 = b2[e],              b21 = b2[128 + e];

    // Phase 1: elementwise fourierGC chain, z into smem spectrum
    for (int f = tid; f < FBINS; f += 512) {
        float xr = embe * d_Xr[b][f];
        float xi = embe * d_Xi[b][f];
        float or1 = fmaxf(xr * d00 - xi * d01 + b00, 0.0f);
        float oi1 = fmaxf(xi * d00 + xr * d01 + b01, 0.0f);
        float pr = sshrink(or1), pi = sshrink(oi1);
        float or2 = fmaxf(or1 * d10 - oi1 * d11 + b10, 0.0f);
        float oi2 = fmaxf(oi1 * d10 + or2 * d11 + b11, 0.0f);   // uses UPDATED or2
        pr += sshrink(or2); pi += sshrink(oi2);
        float or3 = fmaxf(or2 * d20 - oi2 * d21 + b20, 0.0f);
        float oi3 = fmaxf(oi2 * d20 + or3 * d21 + b21, 0.0f);   // uses UPDATED or3
        zb[f] = make_float2(sshrink(or3) + pr, sshrink(oi3) + pi);
    }
    __syncthreads();

    // Phase 2: Hermitian recombination -> G[k], k=0..8191 (in place, pairwise)
    // G[k] = (Z[k]+conj(Z[H-k])) + i * e^{+i*pi*k/8192} * (Z[k]-conj(Z[H-k]))
    // Imag of DC/Nyquist ignored (matches pocketfft c2r).
    for (int k = tid; k <= 4096; k += 512) {
        if (k == 0) {
            float2 Z0 = zb[0], ZN = zb[8192];
            zb[0] = make_float2(Z0.x + ZN.x, Z0.x - ZN.x);
        } else {
            int j = HHALF - k;
            float2 Zk = zb[k], Zj = zb[j];
            float Ax = Zk.x + Zj.x, Ay = Zk.y - Zj.y;
            float Bx = Zk.x - Zj.x, By = Zk.y + Zj.y;
            float sk, ck;
            sincospif((float)k * (1.0f / 8192.0f), &sk, &ck);
            float wBx = ck * Bx - sk * By;
            float wBy = ck * By + sk * Bx;
            zb[k] = make_float2(Ax - wBy,  Ay + wBx);
            zb[j] = make_float2(Ax + wBy, -Ay + wBx);   // k==4096 -> same value, safe
        }
    }
    __syncthreads();

    // Phase 3: in-place radix-2 DIF inverse FFT (e^{+}), natural -> bit-reversed
    for (int s = 0; s < 13; s++) {
        int hh = 4096 >> s;
        for (int t = tid; t < 4096; t += 512) {
            int j = t & (hh - 1);
            int i = ((t >> (12 - s)) << (13 - s)) + j;
            float2 u = zb[i], v = zb[i + hh];
            float dx = u.x - v.x, dy = u.y - v.y;
            zb[i] = make_float2(u.x + v.x, u.y + v.y);
            float2 w = twl[j << s];
            zb[i + hh] = make_float2(dx * w.x - dy * w.y, dx * w.y + dy * w.x);
        }
        __syncthreads();
    }

    // Phase 4: pruned extraction of first 512 real samples + analytic bias
    float* xs = (float*)smg;   // alias first 512 floats of zb
    float2 y = make_float2(0.0f, 0.0f);
    float bias0 = 0.0f, bias1 = 0.0f;
    if (tid < 256) {
        int rn = __brev((unsigned)tid) >> 19;
        y = zb[rn];
        const float* xb = x + b * LSEQ * NFEAT;
        bias0 = xb[(2 * tid) * NFEAT];       // x[b, 2n,   0]
        bias1 = xb[(2 * tid + 1) * NFEAT];   // x[b, 2n+1, 0]
    }
    __syncthreads();
    if (tid < 256) {
        const float inv = 1.0f / 128.0f;     // 1/sqrt(16384)
        xs[2 * tid]     = y.x * inv + bias0 * embe;
        xs[2 * tid + 1] = y.y * inv + bias1 * embe;
    }
    __syncthreads();

    // Phase 5: h[b, e*8 + j] = sum_l xs[l] * emb10[l, j]
    int warp = tid >> 5, lane = tid & 31;
    if (warp < 8) {
        float s = 0.0f;
        for (int l = lane; l < LSEQ; l += 32) s += xs[l] * emb10[l * 8 + warp];
        #pragma unroll
        for (int o = 16; o; o >>= 1) s += __shfl_down_sync(0xFFFFFFFFu, s, o);
        if (lane == 0) d_H1[b][e * 8 + warp] = s;
    }
}

// ---------------------------------------------------------------------------
// Kernel 3: final MLP per batch. 16 blocks x 256 threads.
// ---------------------------------------------------------------------------
__global__ void mlp_kernel(const float* __restrict__ fc1w, const float* __restrict__ fc1b,
                           const float* __restrict__ fc2w, const float* __restrict__ fc2b,
                           const float* __restrict__ fc3w, const float* __restrict__ fc3b,
                           float* __restrict__ out) {
    __shared__ float h[1024];
    __shared__ float v1[64];
    __shared__ float v2[256];
    const int b = blockIdx.x;
    const int tid = threadIdx.x;

    for (int i = tid; i < 1024; i += 256) h[i] = d_H1[b][i];
    __syncthreads();

    int warp = tid >> 5, lane = tid & 31;
    for (int j = warp; j < 64; j += 8) {
        float s = 0.0f;
        for (int k = lane; k < 1024; k += 32) s += h[k] * fc1w[j * 1024 + k];
        #pragma unroll
        for (int o = 16; o; o >>= 1) s += __shfl_down_sync(0xFFFFFFFFu, s, o);
        if (lane == 0) {
            s += fc1b[j];
            v1[j] = s > 0.0f ? s : 0.01f * s;
        }
    }
    __syncthreads();

    {
        int j = tid;   // 256 outputs
        float s = fc2b[j];
        #pragma unroll 8
        for (int k = 0; k < 64; k++) s += v1[k] * fc2w[j * 64 + k];
        v2[j] = s > 0.0f ? s : 0.01f * s;
    }
    __syncthreads();

    if (tid < 96) {
        float s = fc3b[tid];
        #pragma unroll 8
        for (int k = 0; k < 256; k++) s += v2[k] * fc3w[tid * 256 + k];
        out[b * 96 + tid] = s;
    }
}

// ---------------------------------------------------------------------------
extern "C" void kernel_launch(void* const* d_in, const int* in_sizes, int n_in,
                              void* d_out, int out_size) {
    const float* x     = (const float*)d_in[0];
    const float* emb   = (const float*)d_in[1];
    const float* w0    = (const float*)d_in[2];
    const float* b0    = (const float*)d_in[3];
    const float* w1    = (const float*)d_in[4];
    const float* b1    = (const float*)d_in[5];
    const float* w2    = (const float*)d_in[6];
    const float* b2    = (const float*)d_in[7];
    const float* emb10 = (const float*)d_in[8];
    const float* fc1w  = (const float*)d_in[9];
    const float* fc1b  = (const float*)d_in[10];
    const float* fc2w  = (const float*)d_in[11];
    const float* fc2b  = (const float*)d_in[12];
    const float* fc3w  = (const float*)d_in[13];
    const float* fc3b  = (const float*)d_in[14];
    float* out = (float*)d_out;

    static bool attr_set = false;
    const int smem_fwd = (8192 + 4096) * sizeof(float2);          // 98304
    const int smem_gc  = (8200 + 4096) * sizeof(float2);          // 98368
    if (!attr_set) {
        cudaFuncSetAttribute(fwd_fft, cudaFuncAttributeMaxDynamicSharedMemorySize, smem_fwd);
        cudaFuncSetAttribute(gc_ifft, cudaFuncAttributeMaxDynamicSharedMemorySize, smem_gc);
        attr_set = true;
    }

    twiddle_init<<<8, 512>>>();
    fwd_fft<<<NB, 512, smem_fwd>>>(x);
    gc_ifft<<<dim3(EDIM, NB), 512, smem_gc>>>(x, emb, w0, b0, w1, b1, w2, b2, emb10);
    mlp_kernel<<<NB, 256>>>(fc1w, fc1b, fc2w, fc2b, fc3w, fc3b, out);
}

// round 2
// speedup vs baseline: 3.5986x; 3.5986x over previous
#include <cuda_runtime.h>
#include <math.h>

// Problem constants
#define EDIM   128
#define LSEQ   512
#define NB     16
#define NFEAT  32
#define MFULL  16384
#define HHALF  8192
#define FBINS  8193
#define LAMBDA 0.01f

// Persistent scratch (device globals)
__device__ float  d_Xr[NB][FBINS];
__device__ float  d_Xi[NB][FBINS];
__device__ float  d_H1[NB][EDIM * 8];
__device__ float2 d_tw[HHALF / 2];          // e^{+2*pi*i*j/8192}
__device__ float  d_TA[FBINS][8];           // irfft+emb10 folded cos table
__device__ float  d_TB[FBINS][8];           // irfft+emb10 folded sin table
__device__ float  d_P[NB][8];               // bias projection

__device__ __forceinline__ float sshrink(float v) {
    return v > LAMBDA ? v - LAMBDA : (v < -LAMBDA ? v + LAMBDA : 0.0f);
}

// ---------------------------------------------------------------------------
// Kernel 0: twiddle table for the forward FFT
// ---------------------------------------------------------------------------
__global__ void twiddle_init() {
    int j = blockIdx.x * blockDim.x + threadIdx.x;
    if (j < 4096) {
        float s, c;
        sincospif((float)j * (1.0f / 4096.0f), &s, &c);
        d_tw[j] = make_float2(c, s);
    }
}

// ---------------------------------------------------------------------------
// Kernel 1: forward rfft of xt[b, 0:16384] via packed 8192-pt complex FFT.
// ---------------------------------------------------------------------------
__global__ void fwd_fft(const float* __restrict__ x) {
    extern __shared__ float2 smf[];
    float2* buf = smf;           // 8192 complex
    float2* twl = smf + 8192;    // 4096 twiddles
    const int b = blockIdx.x;
    const int tid = threadIdx.x;

    for (int j = tid; j < 4096; j += 512) twl[j] = d_tw[j];

    const float* xb = x + b * LSEQ * NFEAT;
    for (int n = tid; n < HHALF; n += 512) {
        int br = __brev((unsigned)n) >> 19;
        int m0 = 2 * br, m1 = m0 + 1;
        float a = xb[(m0 & 511) * NFEAT + (m0 >> 9)];
        float c = xb[(m1 & 511) * NFEAT + (m1 >> 9)];
        buf[n] = make_float2(a, c);
    }
    __syncthreads();

    for (int s = 0; s < 13; s++) {
        int half = 1 << s;
        for (int t = tid; t < 4096; t += 512) {
            int j = t & (half - 1);
            int i = ((t >> s) << (s + 1)) + j;
            float2 w = twl[j << (12 - s)];
            float2 u = buf[i];
            float2 v = buf[i + half];
            float vr = v.x * w.x + v.y * w.y;     // v * conj(w)
            float vi = v.y * w.x - v.x * w.y;
            buf[i]        = make_float2(u.x + vr, u.y + vi);
            buf[i + half] = make_float2(u.x - vr, u.y - vi);
        }
        __syncthreads();
    }

    const float sc = 0.5f / 128.0f;
    for (int f = tid; f < FBINS; f += 512) {
        float2 Yf = buf[f & (HHALF - 1)];
        float2 Yh = buf[(HHALF - f) & (HHALF - 1)];
        float Ax = Yf.x + Yh.x, Ay = Yf.y - Yh.y;
        float Bx = Yf.x - Yh.x, By = Yf.y + Yh.y;
        float ss, cc;
        sincospif((float)f * (1.0f / 8192.0f), &ss, &cc);
        d_Xr[b][f] = sc * (Ax + cc * By - ss * Bx);
        d_Xi[b][f] = sc * (Ay - cc * Bx - ss * By);
    }
}

// ---------------------------------------------------------------------------
// Kernel 2: build TA/TB tables. TA[f,j] = s_f * sum_l cos(2pi f l/M) E[l,j],
// TB[f,j] = -s_f * sum_l sin(2pi f l/M) E[l,j]. Phase recurrence + resync.
// Grid: 129 blocks x 512 threads (64 f per block, 8 j per f).
// ---------------------------------------------------------------------------
__global__ void build_tables(const float* __restrict__ emb10) {
    __shared__ float E[LSEQ * 8];
    const int tid = threadIdx.x;
    for (int i = tid; i < LSEQ * 8; i += 512) E[i] = emb10[i];
    __syncthreads();

    const int fl = tid >> 3, j = tid & 7;
    const int f = blockIdx.x * 64 + fl;
    if (f > 8192) return;

    float cs, ss;
    sincospif((float)f * (1.0f / 8192.0f), &ss, &cs);   // step e^{i*2pi*f/M}

    float c = 1.0f, s = 0.0f;
    float a = 0.0f, bsum = 0.0f;
    for (int l = 0; l < LSEQ; l++) {
        if ((l & 63) == 0) {                            // exact resync
            int ph = (f * l) & 16383;
            sincospif((float)ph * (1.0f / 8192.0f), &s, &c);
        }
        float ev = E[l * 8 + j];
        a    = fmaf(c, ev, a);
        bsum = fmaf(s, ev, bsum);
        float cn = fmaf(c, cs, -s * ss);
        float sn = fmaf(s, cs,  c * ss);
        c = cn; s = sn;
    }
    float sf = (f == 0 || f == 8192) ? (1.0f / 128.0f) : (2.0f / 128.0f);
    d_TA[f][j] =  sf * a;
    d_TB[f][j] = -sf * bsum;
}

// ---------------------------------------------------------------------------
// Kernel 3: bias projection P[b,j] = sum_l x[b,l,0] * emb10[l,j]
// ---------------------------------------------------------------------------
__global__ void build_P(const float* __restrict__ x, const float* __restrict__ emb10) {
    __shared__ float xs[LSEQ];
    const int b = blockIdx.x, tid = threadIdx.x;   // 256 threads
    for (int l = tid; l < LSEQ; l += 256) xs[l] = x[(b * LSEQ + l) * NFEAT];
    __syncthreads();
    int w = tid >> 5, lane = tid & 31;
    if (w < 8) {
        float s = 0.0f;
        for (int l = lane; l < LSEQ; l += 32) s += xs[l] * emb10[l * 8 + w];
        #pragma unroll
        for (int o = 16; o; o >>= 1) s += __shfl_down_sync(0xFFFFFFFFu, s, o);
        if (lane == 0) d_P[b][w] = s;
    }
}

// ---------------------------------------------------------------------------
// Kernel 4: fused fourierGC + (irfft . emb10) contraction.
// Block = (e-octet, b). 256 threads sweep f; each thread holds 8 e's worth
// of chain constants and 64 accumulators. h[b,e,j] = sum_f zr*TA + zi*TB.
// ---------------------------------------------------------------------------
__global__ void __launch_bounds__(256, 1)
gc_gemm(const float* __restrict__ emb,
        const float* __restrict__ w0, const float* __restrict__ b0,
        const float* __restrict__ w1, const float* __restrict__ b1,
        const float* __restrict__ w2, const float* __restrict__ b2) {
    const int e0 = blockIdx.x * 8;
    const int b  = blockIdx.y;
    const int tid = threadIdx.x;

    float D00[8], D01[8], C00[8], C01[8];
    float d10[8], d11[8], C10[8], C11[8];
    float d20[8], d21[8], C20[8], C21[8];
    #pragma unroll
    for (int eo = 0; eo < 8; eo++) {
        int e = e0 + eo;
        float em = emb[e];
        D00[eo] = em * w0[e * 129];  D01[eo] = em * w0[16384 + e * 129];
        C00[eo] = b0[e];             C01[eo] = b0[128 + e];
        d10[eo] = w1[e * 129];       d11[eo] = w1[16384 + e * 129];
        C10[eo] = b1[e];             C11[eo] = b1[128 + e];
        d20[eo] = w2[e * 129];       d21[eo] = w2[16384 + e * 129];
        C20[eo] = b2[e];             C21[eo] = b2[128 + e];
    }

    float acc[8][8];
    #pragma unroll
    for (int eo = 0; eo < 8; eo++)
        #pragma unroll
        for (int j = 0; j < 8; j++) acc[eo][j] = 0.0f;

    for (int f = tid; f < FBINS; f += 256) {
        float xr = d_Xr[b][f];
        float xi = d_Xi[b][f];
        float4 ta0 = *(const float4*)&d_TA[f][0];
        float4 ta1 = *(const float4*)&d_TA[f][4];
        float4 tb0 = *(const float4*)&d_TB[f][0];
        float4 tb1 = *(const float4*)&d_TB[f][4];
        #pragma unroll
        for (int eo = 0; eo < 8; eo++) {
            float or1 = fmaxf(fmaf(xr, D00[eo], fmaf(-xi, D01[eo], C00[eo])), 0.0f);
            float oi1 = fmaxf(fmaf(xi, D00[eo], fmaf( xr, D01[eo], C01[eo])), 0.0f);
            float pr = sshrink(or1), pi = sshrink(oi1);
            float or2 = fmaxf(fmaf(or1, d10[eo], fmaf(-oi1, d11[eo], C10[eo])), 0.0f);
            float oi2 = fmaxf(fmaf(oi1, d10[eo], fmaf( or2, d11[eo], C11[eo])), 0.0f);
            pr += sshrink(or2); pi += sshrink(oi2);
            float or3 = fmaxf(fmaf(or2, d20[eo], fmaf(-oi2, d21[eo], C20[eo])), 0.0f);
            float oi3 = fmaxf(fmaf(oi2, d20[eo], fmaf( or3, d21[eo], C21[eo])), 0.0f);
            float zr = sshrink(or3) + pr;
            float zi = sshrink(oi3) + pi;
            acc[eo][0] = fmaf(zr, ta0.x, fmaf(zi, tb0.x, acc[eo][0]));
            acc[eo][1] = fmaf(zr, ta0.y, fmaf(zi, tb0.y, acc[eo][1]));
            acc[eo][2] = fmaf(zr, ta0.z, fmaf(zi, tb0.z, acc[eo][2]));
            acc[eo][3] = fmaf(zr, ta0.w, fmaf(zi, tb0.w, acc[eo][3]));
            acc[eo][4] = fmaf(zr, ta1.x, fmaf(zi, tb1.x, acc[eo][4]));
            acc[eo][5] = fmaf(zr, ta1.y, fmaf(zi, tb1.y, acc[eo][5]));
            acc[eo][6] = fmaf(zr, ta1.z, fmaf(zi, tb1.z, acc[eo][6]));
            acc[eo][7] = fmaf(zr, ta1.w, fmaf(zi, tb1.w, acc[eo][7]));
        }
    }

    // Block reduction: warp shuffle then smem across 8 warps
    __shared__ float red[8][64];
    const int lane = tid & 31, w = tid >> 5;
    #pragma unroll
    for (int eo = 0; eo < 8; eo++) {
        #pragma unroll
        for (int j = 0; j < 8; j++) {
            float v = acc[eo][j];
            #pragma unroll
            for (int o = 16; o; o >>= 1) v += __shfl_down_sync(0xFFFFFFFFu, v, o);
            if (lane == 0) red[w][eo * 8 + j] = v;
        }
    }
    __syncthreads();
    if (tid < 64) {
        float s = 0.0f;
        #pragma unroll
        for (int ww = 0; ww < 8; ww++) s += red[ww][tid];
        int e = e0 + (tid >> 3);
        s += emb[e] * d_P[b][tid & 7];        // analytic bias term
        d_H1[b][e0 * 8 + tid] = s;
    }
}

// ---------------------------------------------------------------------------
// Kernel 5: final MLP, 16 blocks x 512 threads, vectorized.
// ---------------------------------------------------------------------------
__global__ void mlp_kernel(const float* __restrict__ fc1w, const float* __restrict__ fc1b,
                           const float* __restrict__ fc2w, const float* __restrict__ fc2b,
                           const float* __restrict__ fc3w, const float* __restrict__ fc3b,
                           float* __restrict__ out) {
    __shared__ __align__(16) float h[1024];
    __shared__ __align__(16) float v1[64];
    __shared__ __align__(16) float v2[256];
    const int b = blockIdx.x;
    const int tid = threadIdx.x;   // 512

    for (int i = tid; i < 1024; i += 512) h[i] = d_H1[b][i];
    __syncthreads();

    const int w = tid >> 5, lane = tid & 31;
    const float4* h4 = (const float4*)h;
    #pragma unroll
    for (int r = 0; r < 4; r++) {
        int j = w + 16 * r;
        const float4* fw = (const float4*)(fc1w + j * 1024);
        float s = 0.0f;
        #pragma unroll
        for (int i = 0; i < 8; i++) {
            float4 a = fw[lane + 32 * i];
            float4 v = h4[lane + 32 * i];
            s += a.x * v.x + a.y * v.y + a.z * v.z + a.w * v.w;
        }
        #pragma unroll
        for (int o = 16; o; o >>= 1) s += __shfl_down_sync(0xFFFFFFFFu, s, o);
        if (lane == 0) {
            s += fc1b[j];
            v1[j] = s > 0.0f ? s : 0.01f * s;
        }
    }
    __syncthreads();

    if (tid < 256) {
        const float4* fw = (const float4*)(fc2w + tid * 64);
        const float4* v14 = (const float4*)v1;
        float s = fc2b[tid];
        #pragma unroll
        for (int i = 0; i < 16; i++) {
            float4 a = fw[i]; float4 v = v14[i];
            s += a.x * v.x + a.y * v.y + a.z * v.z + a.w * v.w;
        }
        v2[tid] = s > 0.0f ? s : 0.01f * s;
    }
    __syncthreads();

    if (tid < 96) {
        const float4* fw = (const float4*)(fc3w + tid * 256);
        const float4* v24 = (const float4*)v2;
        float s = fc3b[tid];
        #pragma unroll
        for (int i = 0; i < 64; i++) {
            float4 a = fw[i]; float4 v = v24[i];
            s += a.x * v.x + a.y * v.y + a.z * v.z + a.w * v.w;
        }
        out[b * 96 + tid] = s;
    }
}

// ---------------------------------------------------------------------------
extern "C" void kernel_launch(void* const* d_in, const int* in_sizes, int n_in,
                              void* d_out, int out_size) {
    const float* x     = (const float*)d_in[0];
    const float* emb   = (const float*)d_in[1];
    const float* w0    = (const float*)d_in[2];
    const float* b0    = (const float*)d_in[3];
    const float* w1    = (const float*)d_in[4];
    const float* b1    = (const float*)d_in[5];
    const float* w2    = (const float*)d_in[6];
    const float* b2    = (const float*)d_in[7];
    const float* emb10 = (const float*)d_in[8];
    const float* fc1w  = (const float*)d_in[9];
    const float* fc1b  = (const float*)d_in[10];
    const float* fc2w  = (const float*)d_in[11];
    const float* fc2b  = (const float*)d_in[12];
    const float* fc3w  = (const float*)d_in[13];
    const float* fc3b  = (const float*)d_in[14];
    float* out = (float*)d_out;

    static bool attr_set = false;
    const int smem_fwd = (8192 + 4096) * sizeof(float2);   // 98304
    if (!attr_set) {
        cudaFuncSetAttribute(fwd_fft, cudaFuncAttributeMaxDynamicSharedMemorySize, smem_fwd);
        attr_set = true;
    }

    twiddle_init<<<8, 512>>>();
    build_tables<<<129, 512>>>(emb10);
    build_P<<<NB, 256>>>(x, emb10);
    fwd_fft<<<NB, 512, smem_fwd>>>(x);
    gc_gemm<<<dim3(EDIM / 8, NB), 256>>>(emb, w0, b0, w1, b1, w2, b2);
    mlp_kernel<<<NB, 512>>>(fc1w, fc1b, fc2w, fc2b, fc3w, fc3b, out);
}

// round 3
// speedup vs baseline: 4.2339x; 1.1765x over previous
#include <cuda_runtime.h>
#include <math.h>

// Problem constants
#define EDIM   128
#define LSEQ   512
#define NB     16
#define NFEAT  32
#define MFULL  16384
#define FBINS  8193
#define LAMBDA 0.01f

// Persistent scratch (device globals)
__device__ float  d_Xr[NB][FBINS];
__device__ float  d_Xi[NB][FBINS];
__device__ float2 d_Y[NB][NFEAT][LSEQ];     // stage-A output (twiddled)
__device__ float  d_H1[NB][EDIM * 8];
__device__ float  d_TA[FBINS][8];           // irfft+emb10 folded cos table
__device__ float  d_TB[FBINS][8];           // irfft+emb10 folded sin table
__device__ float  d_P[NB][8];               // bias projection

__device__ __forceinline__ float sshrink(float v) {
    return v > LAMBDA ? v - LAMBDA : (v < -LAMBDA ? v + LAMBDA : 0.0f);
}

// ---------------------------------------------------------------------------
// Kernel 1a: stage A of the forward rfft.
// For each (b,l): 32-pt DFT over features q, times e^{-2pi i r l / 16384}.
// Grid (64, NB) x 256 threads; warp w handles l = blockIdx.x*8 + w, lane = r.
// ---------------------------------------------------------------------------
__global__ void fft_stageA(const float* __restrict__ x) {
    __shared__ float2 W32[32];     // e^{-2pi i k/32}
    const int tid = threadIdx.x;
    if (tid < 32) {
        float s, c;
        sincospif((float)tid * (1.0f / 16.0f), &s, &c);
        W32[tid] = make_float2(c, -s);
    }
    __syncthreads();

    const int b = blockIdx.y;
    const int l = blockIdx.x * 8 + (tid >> 5);
    const int r = tid & 31;

    float xq = x[(b * LSEQ + l) * NFEAT + r];   // coalesced 128B per warp
    float sr = 0.0f, si = 0.0f;
    #pragma unroll
    for (int q = 0; q < 32; q++) {
        float xv = __shfl_sync(0xFFFFFFFFu, xq, q);
        float2 w = W32[(r * q) & 31];
        sr = fmaf(xv, w.x, sr);
        si = fmaf(xv, w.y, si);
    }
    // input twiddle e^{-2pi i r l / 16384}
    float a = (float)(r * l) * (1.0f / 8192.0f);
    float ss, cc;
    sincospif(a, &ss, &cc);
    float yr = fmaf(sr, cc,  si * ss);      // (sr + i si)(cc - i ss)
    float yi = fmaf(si, cc, -sr * ss);
    d_Y[b][r][l] = make_float2(yr, yi);
}

// ---------------------------------------------------------------------------
// Kernel 1b: stage B. 512-pt complex FFT over l per (r,b); write X[32t+r]
// for f<=8192, ortho scale. Grid (32, NB) x 256 threads.
// ---------------------------------------------------------------------------
__global__ void fft_stageB() {
    __shared__ float2 buf[512];
    __shared__ float2 tw[256];     // e^{-2pi i j/512}
    const int r = blockIdx.x;
    const int b = blockIdx.y;
    const int tid = threadIdx.x;

    {
        float s, c;
        sincospif((float)tid * (1.0f / 256.0f), &s, &c);
        tw[tid] = make_float2(c, -s);
    }
    #pragma unroll
    for (int k = 0; k < 2; k++) {
        int n = tid + 256 * k;
        int br = __brev((unsigned)n) >> 23;   // 9-bit reverse
        buf[n] = d_Y[b][r][br];
    }
    __syncthreads();

    #pragma unroll
    for (int s = 0; s < 9; s++) {
        int half = 1 << s;
        int t = tid;
        int j = t & (half - 1);
        int i = ((t >> s) << (s + 1)) + j;
        float2 w = tw[j << (8 - s)];
        float2 u = buf[i];
        float2 v = buf[i + half];
        float vr = v.x * w.x - v.y * w.y;
        float vi = v.x * w.y + v.y * w.x;
        buf[i]        = make_float2(u.x + vr, u.y + vi);
        buf[i + half] = make_float2(u.x - vr, u.y - vi);
        __syncthreads();
    }

    const float sc = 1.0f / 128.0f;
    #pragma unroll
    for (int k = 0; k < 2; k++) {
        int t = tid + 256 * k;
        int f = 32 * t + r;
        if (f <= 8192) {
            d_Xr[b][f] = buf[t].x * sc;
            d_Xi[b][f] = buf[t].y * sc;
        }
    }
}

// ---------------------------------------------------------------------------
// Kernel 2: build TA/TB tables (irfft basis folded with emb10).
// ---------------------------------------------------------------------------
__global__ void build_tables(const float* __restrict__ emb10) {
    __shared__ float E[LSEQ * 8];
    const int tid = threadIdx.x;
    for (int i = tid; i < LSEQ * 8; i += 512) E[i] = emb10[i];
    __syncthreads();

    const int fl = tid >> 3, j = tid & 7;
    const int f = blockIdx.x * 64 + fl;
    if (f > 8192) return;

    float cs, ss;
    sincospif((float)f * (1.0f / 8192.0f), &ss, &cs);

    float c = 1.0f, s = 0.0f;
    float a = 0.0f, bsum = 0.0f;
    for (int l = 0; l < LSEQ; l++) {
        if ((l & 63) == 0) {
            int ph = (f * l) & 16383;
            sincospif((float)ph * (1.0f / 8192.0f), &s, &c);
        }
        float ev = E[l * 8 + j];
        a    = fmaf(c, ev, a);
        bsum = fmaf(s, ev, bsum);
        float cn = fmaf(c, cs, -s * ss);
        float sn = fmaf(s, cs,  c * ss);
        c = cn; s = sn;
    }
    float sf = (f == 0 || f == 8192) ? (1.0f / 128.0f) : (2.0f / 128.0f);
    d_TA[f][j] =  sf * a;
    d_TB[f][j] = -sf * bsum;
}

// ---------------------------------------------------------------------------
// Kernel 3: bias projection P[b,j] = sum_l x[b,l,0] * emb10[l,j]
// ---------------------------------------------------------------------------
__global__ void build_P(const float* __restrict__ x, const float* __restrict__ emb10) {
    __shared__ float xs[LSEQ];
    const int b = blockIdx.x, tid = threadIdx.x;
    for (int l = tid; l < LSEQ; l += 256) xs[l] = x[(b * LSEQ + l) * NFEAT];
    __syncthreads();
    int w = tid >> 5, lane = tid & 31;
    if (w < 8) {
        float s = 0.0f;
        for (int l = lane; l < LSEQ; l += 32) s += xs[l] * emb10[l * 8 + w];
        #pragma unroll
        for (int o = 16; o; o >>= 1) s += __shfl_down_sync(0xFFFFFFFFu, s, o);
        if (lane == 0) d_P[b][w] = s;
    }
}

// ---------------------------------------------------------------------------
// Kernel 4: fused fourierGC + (irfft . emb10) contraction.
// ---------------------------------------------------------------------------
__global__ void __launch_bounds__(256, 1)
gc_gemm(const float* __restrict__ emb,
        const float* __restrict__ w0, const float* __restrict__ b0,
        const float* __restrict__ w1, const float* __restrict__ b1,
        const float* __restrict__ w2, const float* __restrict__ b2) {
    const int e0 = blockIdx.x * 8;
    const int b  = blockIdx.y;
    const int tid = threadIdx.x;

    float D00[8], D01[8], C00[8], C01[8];
    float d10[8], d11[8], C10[8], C11[8];
    float d20[8], d21[8], C20[8], C21[8];
    #pragma unroll
    for (int eo = 0; eo < 8; eo++) {
        int e = e0 + eo;
        float em = emb[e];
        D00[eo] = em * w0[e * 129];  D01[eo] = em * w0[16384 + e * 129];
        C00[eo] = b0[e];             C01[eo] = b0[128 + e];
        d10[eo] = w1[e * 129];       d11[eo] = w1[16384 + e * 129];
        C10[eo] = b1[e];             C11[eo] = b1[128 + e];
        d20[eo] = w2[e * 129];       d21[eo] = w2[16384 + e * 129];
        C20[eo] = b2[e];             C21[eo] = b2[128 + e];
    }

    float acc[8][8];
    #pragma unroll
    for (int eo = 0; eo < 8; eo++)
        #pragma unroll
        for (int j = 0; j < 8; j++) acc[eo][j] = 0.0f;

    for (int f = tid; f < FBINS; f += 256) {
        float xr = d_Xr[b][f];
        float xi = d_Xi[b][f];
        float4 ta0 = *(const float4*)&d_TA[f][0];
        float4 ta1 = *(const float4*)&d_TA[f][4];
        float4 tb0 = *(const float4*)&d_TB[f][0];
        float4 tb1 = *(const float4*)&d_TB[f][4];
        #pragma unroll
        for (int eo = 0; eo < 8; eo++) {
            float or1 = fmaxf(fmaf(xr, D00[eo], fmaf(-xi, D01[eo], C00[eo])), 0.0f);
            float oi1 = fmaxf(fmaf(xi, D00[eo], fmaf( xr, D01[eo], C01[eo])), 0.0f);
            float pr = sshrink(or1), pi = sshrink(oi1);
            float or2 = fmaxf(fmaf(or1, d10[eo], fmaf(-oi1, d11[eo], C10[eo])), 0.0f);
            float oi2 = fmaxf(fmaf(oi1, d10[eo], fmaf( or2, d11[eo], C11[eo])), 0.0f);
            pr += sshrink(or2); pi += sshrink(oi2);
            float or3 = fmaxf(fmaf(or2, d20[eo], fmaf(-oi2, d21[eo], C20[eo])), 0.0f);
            float oi3 = fmaxf(fmaf(oi2, d20[eo], fmaf( or3, d21[eo], C21[eo])), 0.0f);
            float zr = sshrink(or3) + pr;
            float zi = sshrink(oi3) + pi;
            acc[eo][0] = fmaf(zr, ta0.x, fmaf(zi, tb0.x, acc[eo][0]));
            acc[eo][1] = fmaf(zr, ta0.y, fmaf(zi, tb0.y, acc[eo][1]));
            acc[eo][2] = fmaf(zr, ta0.z, fmaf(zi, tb0.z, acc[eo][2]));
            acc[eo][3] = fmaf(zr, ta0.w, fmaf(zi, tb0.w, acc[eo][3]));
            acc[eo][4] = fmaf(zr, ta1.x, fmaf(zi, tb1.x, acc[eo][4]));
            acc[eo][5] = fmaf(zr, ta1.y, fmaf(zi, tb1.y, acc[eo][5]));
            acc[eo][6] = fmaf(zr, ta1.z, fmaf(zi, tb1.z, acc[eo][6]));
            acc[eo][7] = fmaf(zr, ta1.w, fmaf(zi, tb1.w, acc[eo][7]));
        }
    }

    __shared__ float red[8][64];
    const int lane = tid & 31, w = tid >> 5;
    #pragma unroll
    for (int eo = 0; eo < 8; eo++) {
        #pragma unroll
        for (int j = 0; j < 8; j++) {
            float v = acc[eo][j];
            #pragma unroll
            for (int o = 16; o; o >>= 1) v += __shfl_down_sync(0xFFFFFFFFu, v, o);
            if (lane == 0) red[w][eo * 8 + j] = v;
        }
    }
    __syncthreads();
    if (tid < 64) {
        float s = 0.0f;
        #pragma unroll
        for (int ww = 0; ww < 8; ww++) s += red[ww][tid];
        int e = e0 + (tid >> 3);
        s += emb[e] * d_P[b][tid & 7];
        d_H1[b][e0 * 8 + tid] = s;
    }
}

// ---------------------------------------------------------------------------
// Kernel 5: final MLP, 16 blocks x 512 threads.
// ---------------------------------------------------------------------------
__global__ void mlp_kernel(const float* __restrict__ fc1w, const float* __restrict__ fc1b,
                           const float* __restrict__ fc2w, const float* __restrict__ fc2b,
                           const float* __restrict__ fc3w, const float* __restrict__ fc3b,
                           float* __restrict__ out) {
    __shared__ __align__(16) float h[1024];
    __shared__ __align__(16) float v1[64];
    __shared__ __align__(16) float v2[256];
    const int b = blockIdx.x;
    const int tid = threadIdx.x;

    for (int i = tid; i < 1024; i += 512) h[i] = d_H1[b][i];
    __syncthreads();

    const int w = tid >> 5, lane = tid & 31;
    const float4* h4 = (const float4*)h;
    #pragma unroll
    for (int r = 0; r < 4; r++) {
        int j = w + 16 * r;
        const float4* fw = (const float4*)(fc1w + j * 1024);
        float s = 0.0f;
        #pragma unroll
        for (int i = 0; i < 8; i++) {
            float4 a = fw[lane + 32 * i];
            float4 v = h4[lane + 32 * i];
            s += a.x * v.x + a.y * v.y + a.z * v.z + a.w * v.w;
        }
        #pragma unroll
        for (int o = 16; o; o >>= 1) s += __shfl_down_sync(0xFFFFFFFFu, s, o);
        if (lane == 0) {
            s += fc1b[j];
            v1[j] = s > 0.0f ? s : 0.01f * s;
        }
    }
    __syncthreads();

    if (tid < 256) {
        const float4* fw = (const float4*)(fc2w + tid * 64);
        const float4* v14 = (const float4*)v1;
        float s = fc2b[tid];
        #pragma unroll
        for (int i = 0; i < 16; i++) {
            float4 a = fw[i]; float4 v = v14[i];
            s += a.x * v.x + a.y * v.y + a.z * v.z + a.w * v.w;
        }
        v2[tid] = s > 0.0f ? s : 0.01f * s;
    }
    __syncthreads();

    if (tid < 96) {
        const float4* fw = (const float4*)(fc3w + tid * 256);
        const float4* v24 = (const float4*)v2;
        float s = fc3b[tid];
        #pragma unroll
        for (int i = 0; i < 64; i++) {
            float4 a = fw[i]; float4 v = v24[i];
            s += a.x * v.x + a.y * v.y + a.z * v.z + a.w * v.w;
        }
        out[b * 96 + tid] = s;
    }
}

// ---------------------------------------------------------------------------
extern "C" void kernel_launch(void* const* d_in, const int* in_sizes, int n_in,
                              void* d_out, int out_size) {
    const float* x     = (const float*)d_in[0];
    const float* emb   = (const float*)d_in[1];
    const float* w0    = (const float*)d_in[2];
    const float* b0    = (const float*)d_in[3];
    const float* w1    = (const float*)d_in[4];
    const float* b1    = (const float*)d_in[5];
    const float* w2    = (const float*)d_in[6];
    const float* b2    = (const float*)d_in[7];
    const float* emb10 = (const float*)d_in[8];
    const float* fc1w  = (const float*)d_in[9];
    const float* fc1b  = (const float*)d_in[10];
    const float* fc2w  = (const float*)d_in[11];
    const float* fc2b  = (const float*)d_in[12];
    const float* fc3w  = (const float*)d_in[13];
    const float* fc3b  = (const float*)d_in[14];
    float* out = (float*)d_out;

    fft_stageA<<<dim3(64, NB), 256>>>(x);
    build_tables<<<129, 512>>>(emb10);
    build_P<<<NB, 256>>>(x, emb10);
    fft_stageB<<<dim3(32, NB), 256>>>();
    gc_gemm<<<dim3(EDIM / 8, NB), 256>>>(emb, w0, b0, w1, b1, w2, b2);
    mlp_kernel<<<NB, 512>>>(fc1w, fc1b, fc2w, fc2b, fc3w, fc3b, out);
}

// round 4
// speedup vs baseline: 4.4392x; 1.0485x over previous
#include <cuda_runtime.h>
#include <math.h>

// Problem constants
#define EDIM   128
#define LSEQ   512
#define NB     16
#define NFEAT  32
#define FBINS  8193
#define LAMBDA 0.01f

// Persistent scratch (device globals)
__device__ float2 d_X[NB][FBINS];           // forward spectrum (ortho)
__device__ float  d_H1[NB][EDIM * 8];
__device__ float  d_TA[FBINS][8];           // irfft+emb10 folded cos table
__device__ float  d_TB[FBINS][8];           // irfft+emb10 folded sin table

__device__ __forceinline__ float sshrink(float v) {
    return v > LAMBDA ? v - LAMBDA : (v < -LAMBDA ? v + LAMBDA : 0.0f);
}

// ---------------------------------------------------------------------------
// Kernel 1 (fused forward rfft): block = (r, b). Loads x[b] (64KB, padded),
// computes the 32-pt feature DFT for frequency residue r over all l, applies
// the CT twiddle, then a 512-pt complex FFT over l. Writes X[32t+r].
// Grid (32, NB) x 256 threads.
// ---------------------------------------------------------------------------
__global__ void __launch_bounds__(256)
fwd_fused(const float* __restrict__ x) {
    extern __shared__ float sm[];
    float*  xs  = sm;                        // 512*33 floats (padded rows)
    float2* buf = (float2*)(sm + 512 * 33);  // 512 complex
    float2* tw  = buf + 512;                 // 256 twiddles e^{-2pi i j/512}
    float2* w32 = tw + 256;                  // 32 twiddles e^{-2pi i r q/32}

    const int r = blockIdx.x;
    const int b = blockIdx.y;
    const int tid = threadIdx.x;

    // load x[b] coalesced into padded smem
    const float* xb = x + b * LSEQ * NFEAT;
    #pragma unroll
    for (int k = 0; k < 64; k++) {
        int idx = tid + 256 * k;
        xs[(idx >> 5) * 33 + (idx & 31)] = xb[idx];
    }
    {
        float s, c;
        sincospif((float)tid * (1.0f / 256.0f), &s, &c);
        tw[tid] = make_float2(c, -s);
    }
    if (tid < 32) {
        int ph = (r * tid) & 31;
        float s, c;
        sincospif((float)ph * (1.0f / 16.0f), &s, &c);
        w32[tid] = make_float2(c, -s);
    }
    __syncthreads();

    // 32-pt DFT over q for each l (2 per thread) + twiddle, store bit-reversed
    #pragma unroll
    for (int li = 0; li < 2; li++) {
        int l = tid + 256 * li;
        const float* row = xs + l * 33;
        float sr = 0.0f, si = 0.0f;
        #pragma unroll
        for (int q = 0; q < 32; q++) {
            float xv = row[q];
            float2 w = w32[q];
            sr = fmaf(xv, w.x, sr);
            si = fmaf(xv, w.y, si);
        }
        // e^{-2pi i r l / 16384}
        float ss, cc;
        sincospif((float)(r * l) * (1.0f / 8192.0f), &ss, &cc);
        float yr = fmaf(sr, cc,  si * ss);
        float yi = fmaf(si, cc, -sr * ss);
        int br = __brev((unsigned)l) >> 23;   // 9-bit reverse
        buf[br] = make_float2(yr, yi);
    }
    __syncthreads();

    // 512-pt DIT FFT
    #pragma unroll
    for (int s = 0; s < 9; s++) {
        int half = 1 << s;
        int j = tid & (half - 1);
        int i = ((tid >> s) << (s + 1)) + j;
        float2 w = tw[j << (8 - s)];
        float2 u = buf[i];
        float2 v = buf[i + half];
        float vr = v.x * w.x - v.y * w.y;
        float vi = v.x * w.y + v.y * w.x;
        buf[i]        = make_float2(u.x + vr, u.y + vi);
        buf[i + half] = make_float2(u.x - vr, u.y - vi);
        __syncthreads();
    }

    const float sc = 1.0f / 128.0f;
    #pragma unroll
    for (int k = 0; k < 2; k++) {
        int t = tid + 256 * k;
        int f = 32 * t + r;
        if (f <= 8192)
            d_X[b][f] = make_float2(buf[t].x * sc, buf[t].y * sc);
    }
}

// ---------------------------------------------------------------------------
// Kernel 2: build TA/TB tables (irfft basis folded with emb10).
// ---------------------------------------------------------------------------
__global__ void build_tables(const float* __restrict__ emb10) {
    __shared__ float E[LSEQ * 8];
    const int tid = threadIdx.x;
    for (int i = tid; i < LSEQ * 8; i += 512) E[i] = emb10[i];
    __syncthreads();

    const int fl = tid >> 3, j = tid & 7;
    const int f = blockIdx.x * 64 + fl;
    if (f > 8192) return;

    float cs, ss;
    sincospif((float)f * (1.0f / 8192.0f), &ss, &cs);

    float c = 1.0f, s = 0.0f;
    float a = 0.0f, bsum = 0.0f;
    for (int l = 0; l < LSEQ; l++) {
        if ((l & 63) == 0) {
            int ph = (f * l) & 16383;
            sincospif((float)ph * (1.0f / 8192.0f), &s, &c);
        }
        float ev = E[l * 8 + j];
        a    = fmaf(c, ev, a);
        bsum = fmaf(s, ev, bsum);
        float cn = fmaf(c, cs, -s * ss);
        float sn = fmaf(s, cs,  c * ss);
        c = cn; s = sn;
    }
    float sf = (f == 0 || f == 8192) ? (1.0f / 128.0f) : (2.0f / 128.0f);
    d_TA[f][j] =  sf * a;
    d_TB[f][j] = -sf * bsum;
}

// ---------------------------------------------------------------------------
// Kernel 3: fused fourierGC + (irfft . emb10) contraction.
// ---------------------------------------------------------------------------
__global__ void __launch_bounds__(256, 1)
gc_gemm(const float* __restrict__ emb,
        const float* __restrict__ w0, const float* __restrict__ b0,
        const float* __restrict__ w1, const float* __restrict__ b1,
        const float* __restrict__ w2, const float* __restrict__ b2) {
    const int e0 = blockIdx.x * 8;
    const int b  = blockIdx.y;
    const int tid = threadIdx.x;

    float D00[8], D01[8], C00[8], C01[8];
    float d10[8], d11[8], C10[8], C11[8];
    float d20[8], d21[8], C20[8], C21[8];
    #pragma unroll
    for (int eo = 0; eo < 8; eo++) {
        int e = e0 + eo;
        float em = emb[e];
        D00[eo] = em * w0[e * 129];  D01[eo] = em * w0[16384 + e * 129];
        C00[eo] = b0[e];             C01[eo] = b0[128 + e];
        d10[eo] = w1[e * 129];       d11[eo] = w1[16384 + e * 129];
        C10[eo] = b1[e];             C11[eo] = b1[128 + e];
        d20[eo] = w2[e * 129];       d21[eo] = w2[16384 + e * 129];
        C20[eo] = b2[e];             C21[eo] = b2[128 + e];
    }

    float acc[8][8];
    #pragma unroll
    for (int eo = 0; eo < 8; eo++)
        #pragma unroll
        for (int j = 0; j < 8; j++) acc[eo][j] = 0.0f;

    for (int f = tid; f < FBINS; f += 256) {
        float2 X = d_X[b][f];
        float xr = X.x, xi = X.y;
        float4 ta0 = *(const float4*)&d_TA[f][0];
        float4 ta1 = *(const float4*)&d_TA[f][4];
        float4 tb0 = *(const float4*)&d_TB[f][0];
        float4 tb1 = *(const float4*)&d_TB[f][4];
        #pragma unroll
        for (int eo = 0; eo < 8; eo++) {
            float or1 = fmaxf(fmaf(xr, D00[eo], fmaf(-xi, D01[eo], C00[eo])), 0.0f);
            float oi1 = fmaxf(fmaf(xi, D00[eo], fmaf( xr, D01[eo], C01[eo])), 0.0f);
            float pr = sshrink(or1), pi = sshrink(oi1);
            float or2 = fmaxf(fmaf(or1, d10[eo], fmaf(-oi1, d11[eo], C10[eo])), 0.0f);
            float oi2 = fmaxf(fmaf(oi1, d10[eo], fmaf( or2, d11[eo], C11[eo])), 0.0f);
            pr += sshrink(or2); pi += sshrink(oi2);
            float or3 = fmaxf(fmaf(or2, d20[eo], fmaf(-oi2, d21[eo], C20[eo])), 0.0f);
            float oi3 = fmaxf(fmaf(oi2, d20[eo], fmaf( or3, d21[eo], C21[eo])), 0.0f);
            float zr = sshrink(or3) + pr;
            float zi = sshrink(oi3) + pi;
            acc[eo][0] = fmaf(zr, ta0.x, fmaf(zi, tb0.x, acc[eo][0]));
            acc[eo][1] = fmaf(zr, ta0.y, fmaf(zi, tb0.y, acc[eo][1]));
            acc[eo][2] = fmaf(zr, ta0.z, fmaf(zi, tb0.z, acc[eo][2]));
            acc[eo][3] = fmaf(zr, ta0.w, fmaf(zi, tb0.w, acc[eo][3]));
            acc[eo][4] = fmaf(zr, ta1.x, fmaf(zi, tb1.x, acc[eo][4]));
            acc[eo][5] = fmaf(zr, ta1.y, fmaf(zi, tb1.y, acc[eo][5]));
            acc[eo][6] = fmaf(zr, ta1.z, fmaf(zi, tb1.z, acc[eo][6]));
            acc[eo][7] = fmaf(zr, ta1.w, fmaf(zi, tb1.w, acc[eo][7]));
        }
    }

    __shared__ float red[8][64];
    const int lane = tid & 31, w = tid >> 5;
    #pragma unroll
    for (int eo = 0; eo < 8; eo++) {
        #pragma unroll
        for (int j = 0; j < 8; j++) {
            float v = acc[eo][j];
            #pragma unroll
            for (int o = 16; o; o >>= 1) v += __shfl_down_sync(0xFFFFFFFFu, v, o);
            if (lane == 0) red[w][eo * 8 + j] = v;
        }
    }
    __syncthreads();
    if (tid < 64) {
        float s = 0.0f;
        #pragma unroll
        for (int ww = 0; ww < 8; ww++) s += red[ww][tid];
        d_H1[b][e0 * 8 + tid] = s;
    }
}

// ---------------------------------------------------------------------------
// Kernel 4: bias projection + final MLP fused. 16 blocks x 512 threads.
// ---------------------------------------------------------------------------
__global__ void __launch_bounds__(512)
mlp_kernel(const float* __restrict__ x, const float* __restrict__ emb,
           const float* __restrict__ emb10,
           const float* __restrict__ fc1w, const float* __restrict__ fc1b,
           const float* __restrict__ fc2w, const float* __restrict__ fc2b,
           const float* __restrict__ fc3w, const float* __restrict__ fc3b,
           float* __restrict__ out) {
    __shared__ __align__(16) float h[1024];
    __shared__ __align__(16) float v1[64];
    __shared__ __align__(16) float v2[256];
    __shared__ float xs[LSEQ];
    __shared__ float Ps[8];
    const int b = blockIdx.x;
    const int tid = threadIdx.x;   // 512
    const int w = tid >> 5, lane = tid & 31;

    // P[b,j] = sum_l x[b,l,0] * emb10[l,j]
    xs[tid] = x[(b * LSEQ + tid) * NFEAT];
    __syncthreads();
    if (w < 8) {
        float s = 0.0f;
        #pragma unroll
        for (int i = 0; i < 16; i++) s += xs[lane + 32 * i] * emb10[(lane + 32 * i) * 8 + w];
        #pragma unroll
        for (int o = 16; o; o >>= 1) s += __shfl_down_sync(0xFFFFFFFFu, s, o);
        if (lane == 0) Ps[w] = s;
    }
    __syncthreads();

    // h = H1 + emb[e] * P[j]
    #pragma unroll
    for (int k = 0; k < 2; k++) {
        int i = tid + 512 * k;
        h[i] = d_H1[b][i] + emb[i >> 3] * Ps[i & 7];
    }
    __syncthreads();

    const float4* h4 = (const float4*)h;
    #pragma unroll
    for (int r = 0; r < 4; r++) {
        int j = w + 16 * r;
        const float4* fw = (const float4*)(fc1w + j * 1024);
        float s = 0.0f;
        #pragma unroll
        for (int i = 0; i < 8; i++) {
            float4 a = fw[lane + 32 * i];
            float4 v = h4[lane + 32 * i];
            s += a.x * v.x + a.y * v.y + a.z * v.z + a.w * v.w;
        }
        #pragma unroll
        for (int o = 16; o; o >>= 1) s += __shfl_down_sync(0xFFFFFFFFu, s, o);
        if (lane == 0) {
            s += fc1b[j];
            v1[j] = s > 0.0f ? s : 0.01f * s;
        }
    }
    __syncthreads();

    if (tid < 256) {
        const float4* fw = (const float4*)(fc2w + tid * 64);
        const float4* v14 = (const float4*)v1;
        float s = fc2b[tid];
        #pragma unroll
        for (int i = 0; i < 16; i++) {
            float4 a = fw[i]; float4 v = v14[i];
            s += a.x * v.x + a.y * v.y + a.z * v.z + a.w * v.w;
        }
        v2[tid] = s > 0.0f ? s : 0.01f * s;
    }
    __syncthreads();

    if (tid < 96) {
        const float4* fw = (const float4*)(fc3w + tid * 256);
        const float4* v24 = (const float4*)v2;
        float s = fc3b[tid];
        #pragma unroll
        for (int i = 0; i < 64; i++) {
            float4 a = fw[i]; float4 v = v24[i];
            s += a.x * v.x + a.y * v.y + a.z * v.z + a.w * v.w;
        }
        out[b * 96 + tid] = s;
    }
}

// ---------------------------------------------------------------------------
extern "C" void kernel_launch(void* const* d_in, const int* in_sizes, int n_in,
                              void* d_out, int out_size) {
    const float* x     = (const float*)d_in[0];
    const float* emb   = (const float*)d_in[1];
    const float* w0    = (const float*)d_in[2];
    const float* b0    = (const float*)d_in[3];
    const float* w1    = (const float*)d_in[4];
    const float* b1    = (const float*)d_in[5];
    const float* w2    = (const float*)d_in[6];
    const float* b2    = (const float*)d_in[7];
    const float* emb10 = (const float*)d_in[8];
    const float* fc1w  = (const float*)d_in[9];
    const float* fc1b  = (const float*)d_in[10];
    const float* fc2w  = (const float*)d_in[11];
    const float* fc2b  = (const float*)d_in[12];
    const float* fc3w  = (const float*)d_in[13];
    const float* fc3b  = (const float*)d_in[14];
    float* out = (float*)d_out;

    // smem for fwd_fused: 512*33 floats + 512 float2 + 256 float2 + 32 float2
    const int smem_fwd = 512 * 33 * 4 + (512 + 256 + 32) * 8;   // 73984
    static bool attr_set = false;
    if (!attr_set) {
        cudaFuncSetAttribute(fwd_fused, cudaFuncAttributeMaxDynamicSharedMemorySize, smem_fwd);
        attr_set = true;
    }

    fwd_fused<<<dim3(32, NB), 256, smem_fwd>>>(x);
    build_tables<<<129, 512>>>(emb10);
    gc_gemm<<<dim3(EDIM / 8, NB), 256>>>(emb, w0, b0, w1, b1, w2, b2);
    mlp_kernel<<<NB, 512>>>(x, emb, emb10, fc1w, fc1b, fc2w, fc2b, fc3w, fc3b, out);
}